// round 7
// baseline (speedup 1.0000x reference)
#include <cuda_runtime.h>

// SPDUnVectorize: out[b,i,j] = x[b, tri(min(i,j), max(i,j))]
// tri(i,j), i<=j: i*N - i*(i-1)/2 + (j-i)
//
// Row-streaming design for DRAM page locality:
//  - CTA = (32 consecutive output rows, batch b). Writes one contiguous
//    32KB stream. No smem, no __syncthreads.
//  - thread = output column j (256 threads = 256 columns).
//  - per row i: val = x[tri(i,j)] if j>=i (coalesced contiguous read)
//               else x[tri(j,i)]  (per-thread sequential -> L1 sector reuse 8x;
//               duplicate reads are L2 hits: batch row is 131KB, L2-resident
//               across its 8 launch-adjacent CTAs).
//  - index recurrences: upper ptr += N-1-i, lower ptr += 1 per row.
//  - __stcs streaming stores (output is write-once; keep L2 for input).

#define NMAT 256
#define DTRI (NMAT * (NMAT + 1) / 2)   // 32896
#define ROWS_PER_CTA 32
#define THREADS 256

__global__ void __launch_bounds__(THREADS)
spd_unvec_rows(const float* __restrict__ x, float* __restrict__ out) {
    const int b  = blockIdx.y;
    const int i0 = blockIdx.x * ROWS_PER_CTA;
    const int j  = threadIdx.x;

    const float* __restrict__ xr = x + (size_t)b * DTRI;
    float* __restrict__ o = out + (size_t)b * (NMAT * NMAT) + (size_t)i0 * NMAT + j;

    // up = tri(i, j) for i <= j   (valid whenever used: j >= i)
    // lo = tri(j, i) for i >= j   (valid whenever used: j <  i)
    int up = i0 * NMAT - (i0 * (i0 - 1)) / 2 + (j - i0);
    int lo = j * NMAT - (j * (j - 1)) / 2 + (i0 - j);

    #pragma unroll
    for (int k = 0; k < ROWS_PER_CTA; k++) {
        const int i = i0 + k;
        const float v = __ldg(xr + ((j >= i) ? up : lo));
        __stcs(o, v);
        o  += NMAT;
        up += NMAT - 1 - i;
        lo += 1;
    }
}

extern "C" void kernel_launch(void* const* d_in, const int* in_sizes, int n_in,
                              void* d_out, int out_size) {
    const float* x = (const float*)d_in[0];
    float* out = (float*)d_out;

    const int B = out_size / (NMAT * NMAT);   // 4096

    dim3 grid(NMAT / ROWS_PER_CTA, B);        // (8, 4096)
    spd_unvec_rows<<<grid, THREADS>>>(x, out);
}